// round 1
// baseline (speedup 1.0000x reference)
#include <cuda_runtime.h>
#include <cstdint>

#define EMBED   1024
#define NHEADS  16
#define HDIM    64
#define BATCH   4
#define SEQ     2048
#define MROWS   (BATCH * SEQ)          // 8192
#define HEADEL  (BATCH * NHEADS * SEQ * HDIM)  // 8388608

// Scratch (static device globals: allocation-free rule)
__device__ float g_Q[HEADEL];
__device__ float g_K[HEADEL];
__device__ float g_V[HEADEL];
__device__ float g_AO[MROWS * EMBED];

// ---------------- helpers ----------------
__device__ __forceinline__ uint32_t f2tf(float x) {
    uint32_t u;
    asm("cvt.rna.tf32.f32 %0, %1;" : "=r"(u) : "f"(x));
    return u;
}
__device__ __forceinline__ float tf32r(float x) {
    return __uint_as_float(f2tf(x));
}
__device__ __forceinline__ void mma8(float* d, const uint32_t* a, const uint32_t* b) {
    asm volatile(
        "mma.sync.aligned.m16n8k8.row.col.f32.tf32.tf32.f32 "
        "{%0,%1,%2,%3},{%4,%5,%6,%7},{%8,%9},{%0,%1,%2,%3};\n"
        : "+f"(d[0]), "+f"(d[1]), "+f"(d[2]), "+f"(d[3])
        : "r"(a[0]), "r"(a[1]), "r"(a[2]), "r"(a[3]), "r"(b[0]), "r"(b[1]));
}

// ---------------- TN GEMM: out = X @ W^T + bias ----------------
// X: [M=8192, K=1024] row-major, W: [N=1024, K=1024] row-major.
// MODE 0: out[m*N + n]   (final projection)
// MODE 1: out[((b*16+h)*SEQ + l)*64 + dh]   (split heads)
template<int MODE>
__global__ __launch_bounds__(256) void gemm_tn(const float* __restrict__ X,
                                               const float* __restrict__ W,
                                               const float* __restrict__ bias,
                                               float* __restrict__ out)
{
    constexpr int K = EMBED, N = EMBED;
    __shared__ float sA[128 * 36];
    __shared__ float sB[128 * 36];

    const int tid  = threadIdx.x;
    const int lane = tid & 31;
    const int wid  = tid >> 5;
    const int wm   = wid & 1;        // 2 warps in M  -> 64-row warp tile
    const int wn   = wid >> 1;       // 4 warps in N  -> 32-col warp tile
    const int r    = lane >> 2;
    const int c    = lane & 3;
    const int bm   = blockIdx.y * 128;
    const int bn   = blockIdx.x * 128;

    float acc[4][4][4];
    #pragma unroll
    for (int mt = 0; mt < 4; ++mt)
        #pragma unroll
        for (int nt = 0; nt < 4; ++nt)
            #pragma unroll
            for (int e = 0; e < 4; ++e) acc[mt][nt][e] = 0.f;

    for (int kt = 0; kt < K; kt += 32) {
        // stage A and B tiles (convert to tf32 at staging)
        #pragma unroll
        for (int i = 0; i < 4; ++i) {
            int e   = tid + i * 256;      // 0..1023
            int row = e >> 3;
            int c4  = (e & 7) * 4;
            float4 va = *reinterpret_cast<const float4*>(X + (size_t)(bm + row) * K + kt + c4);
            float4 vb = *reinterpret_cast<const float4*>(W + (size_t)(bn + row) * K + kt + c4);
            float4 sa = make_float4(tf32r(va.x), tf32r(va.y), tf32r(va.z), tf32r(va.w));
            float4 sb = make_float4(tf32r(vb.x), tf32r(vb.y), tf32r(vb.z), tf32r(vb.w));
            *reinterpret_cast<float4*>(sA + row * 36 + c4) = sa;
            *reinterpret_cast<float4*>(sB + row * 36 + c4) = sb;
        }
        __syncthreads();

        #pragma unroll
        for (int kk = 0; kk < 4; ++kk) {
            uint32_t af[4][4], bf[4][2];
            #pragma unroll
            for (int mt = 0; mt < 4; ++mt) {
                int row0 = wm * 64 + mt * 16 + r;
                af[mt][0] = __float_as_uint(sA[row0 * 36 + kk * 8 + c]);
                af[mt][1] = __float_as_uint(sA[(row0 + 8) * 36 + kk * 8 + c]);
                af[mt][2] = __float_as_uint(sA[row0 * 36 + kk * 8 + c + 4]);
                af[mt][3] = __float_as_uint(sA[(row0 + 8) * 36 + kk * 8 + c + 4]);
            }
            #pragma unroll
            for (int nt = 0; nt < 4; ++nt) {
                int n0 = wn * 32 + nt * 8 + r;
                bf[nt][0] = __float_as_uint(sB[n0 * 36 + kk * 8 + c]);
                bf[nt][1] = __float_as_uint(sB[n0 * 36 + kk * 8 + c + 4]);
            }
            #pragma unroll
            for (int mt = 0; mt < 4; ++mt)
                #pragma unroll
                for (int nt = 0; nt < 4; ++nt)
                    mma8(acc[mt][nt], af[mt], bf[nt]);
        }
        __syncthreads();
    }

    // epilogue: add bias, store
    #pragma unroll
    for (int mt = 0; mt < 4; ++mt) {
        int row0 = bm + wm * 64 + mt * 16 + r;
        #pragma unroll
        for (int nt = 0; nt < 4; ++nt) {
            int col = bn + wn * 32 + nt * 8 + 2 * c;
            float b0 = __ldg(bias + col);
            float b1 = __ldg(bias + col + 1);
            float2 v0 = make_float2(acc[mt][nt][0] + b0, acc[mt][nt][1] + b1);
            float2 v1 = make_float2(acc[mt][nt][2] + b0, acc[mt][nt][3] + b1);
            if (MODE == 0) {
                *reinterpret_cast<float2*>(out + (size_t)row0 * N + col)       = v0;
                *reinterpret_cast<float2*>(out + (size_t)(row0 + 8) * N + col) = v1;
            } else {
                int bb = row0 >> 11;            // batch (2048 rows each)
                int l0 = row0 & (SEQ - 1);
                int h  = col >> 6;
                int dh = col & 63;
                size_t d0 = ((size_t)(bb * NHEADS + h) * SEQ + l0) * HDIM + dh;
                *reinterpret_cast<float2*>(out + d0)                 = v0;
                *reinterpret_cast<float2*>(out + d0 + 8 * HDIM)      = v1;
            }
        }
    }
}

// ---------------- causal flash attention ----------------
// grid: (16 q-tiles, 64 bh), 256 threads. q tile = 128 rows, kv tile = 64 rows.
__global__ __launch_bounds__(256) void attn_kernel(float* __restrict__ outAO)
{
    __shared__ float sm[128 * 68];          // Q staging, then K(64x68)+V(64x68)

    const int tid  = threadIdx.x;
    const int lane = tid & 31;
    const int wid  = tid >> 5;              // 8 warps, 16 q rows each
    const int r    = lane >> 2;
    const int c    = lane & 3;
    const int qt   = 15 - (int)blockIdx.x;  // heavy tiles first
    const int bh   = blockIdx.y;

    const size_t base = (size_t)bh * SEQ * HDIM;
    const float* Qp = g_Q + base;
    const float* Kp = g_K + base;
    const float* Vp = g_V + base;

    // ---- stage Q (scaled by 1/sqrt(Dh)), build A-fragments ----
    #pragma unroll
    for (int i = 0; i < 8; ++i) {
        int e   = tid + i * 256;            // 0..2047 float4s
        int row = e >> 4;
        int c4  = (e & 15) * 4;
        float4 v = *reinterpret_cast<const float4*>(Qp + (size_t)(qt * 128 + row) * HDIM + c4);
        float4 s = make_float4(tf32r(v.x * 0.125f), tf32r(v.y * 0.125f),
                               tf32r(v.z * 0.125f), tf32r(v.w * 0.125f));
        *reinterpret_cast<float4*>(sm + row * 68 + c4) = s;
    }
    __syncthreads();

    uint32_t qa[8][4];
    {
        int row0 = wid * 16 + r;
        #pragma unroll
        for (int kk = 0; kk < 8; ++kk) {
            qa[kk][0] = __float_as_uint(sm[row0 * 68 + kk * 8 + c]);
            qa[kk][1] = __float_as_uint(sm[(row0 + 8) * 68 + kk * 8 + c]);
            qa[kk][2] = __float_as_uint(sm[row0 * 68 + kk * 8 + c + 4]);
            qa[kk][3] = __float_as_uint(sm[(row0 + 8) * 68 + kk * 8 + c + 4]);
        }
    }

    float* kS = sm;
    float* vS = sm + 64 * 68;

    float o[8][4];
    #pragma unroll
    for (int dt = 0; dt < 8; ++dt)
        #pragma unroll
        for (int e = 0; e < 4; ++e) o[dt][e] = 0.f;

    float m0 = -1e30f, m1 = -1e30f, l0 = 0.f, l1 = 0.f;
    const int qrow0 = qt * 128 + wid * 16 + r;   // rows qrow0 and qrow0+8
    const int srcA  = (lane & ~3) | (c >> 1);
    const int srcB  = srcA + 2;
    const bool odd  = (c & 1);

    const int jt_end = 2 * qt + 1;
    for (int jt = 0; jt <= jt_end; ++jt) {
        __syncthreads();    // previous iter consumers done (no-op cost on first iter)
        // ---- stage K and V (tf32) ----
        #pragma unroll
        for (int i = 0; i < 4; ++i) {
            int e   = tid + i * 256;        // 0..1023 float4s per tensor
            int row = e >> 4;
            int c4  = (e & 15) * 4;
            float4 kv = *reinterpret_cast<const float4*>(Kp + (size_t)(jt * 64 + row) * HDIM + c4);
            float4 vv = *reinterpret_cast<const float4*>(Vp + (size_t)(jt * 64 + row) * HDIM + c4);
            *reinterpret_cast<float4*>(kS + row * 68 + c4) =
                make_float4(tf32r(kv.x), tf32r(kv.y), tf32r(kv.z), tf32r(kv.w));
            *reinterpret_cast<float4*>(vS + row * 68 + c4) =
                make_float4(tf32r(vv.x), tf32r(vv.y), tf32r(vv.z), tf32r(vv.w));
        }
        __syncthreads();

        // ---- S = (Q/8) K^T  (128 x 64 per block; 16 x 64 per warp) ----
        float s[8][4];
        #pragma unroll
        for (int nt = 0; nt < 8; ++nt)
            #pragma unroll
            for (int e = 0; e < 4; ++e) s[nt][e] = 0.f;

        #pragma unroll
        for (int kk = 0; kk < 8; ++kk) {
            #pragma unroll
            for (int nt = 0; nt < 8; ++nt) {
                uint32_t bb[2];
                bb[0] = __float_as_uint(kS[(nt * 8 + r) * 68 + kk * 8 + c]);
                bb[1] = __float_as_uint(kS[(nt * 8 + r) * 68 + kk * 8 + c + 4]);
                mma8(s[nt], qa[kk], bb);
            }
        }

        // ---- causal mask (only last two kv tiles can intersect the diagonal) ----
        if (jt >= 2 * qt) {
            #pragma unroll
            for (int nt = 0; nt < 8; ++nt) {
                int kc = jt * 64 + nt * 8 + 2 * c;
                if (kc > qrow0)         s[nt][0] = -1e30f;
                if (kc + 1 > qrow0)     s[nt][1] = -1e30f;
                if (kc > qrow0 + 8)     s[nt][2] = -1e30f;
                if (kc + 1 > qrow0 + 8) s[nt][3] = -1e30f;
            }
        }

        // ---- online softmax ----
        float rmax0 = -1e30f, rmax1 = -1e30f;
        #pragma unroll
        for (int nt = 0; nt < 8; ++nt) {
            rmax0 = fmaxf(rmax0, fmaxf(s[nt][0], s[nt][1]));
            rmax1 = fmaxf(rmax1, fmaxf(s[nt][2], s[nt][3]));
        }
        rmax0 = fmaxf(rmax0, __shfl_xor_sync(0xFFFFFFFFu, rmax0, 1));
        rmax0 = fmaxf(rmax0, __shfl_xor_sync(0xFFFFFFFFu, rmax0, 2));
        rmax1 = fmaxf(rmax1, __shfl_xor_sync(0xFFFFFFFFu, rmax1, 1));
        rmax1 = fmaxf(rmax1, __shfl_xor_sync(0xFFFFFFFFu, rmax1, 2));

        float mn0 = fmaxf(m0, rmax0), mn1 = fmaxf(m1, rmax1);
        float f0 = __expf(m0 - mn0), f1 = __expf(m1 - mn1);
        float rs0 = 0.f, rs1 = 0.f;
        #pragma unroll
        for (int nt = 0; nt < 8; ++nt) {
            s[nt][0] = __expf(s[nt][0] - mn0);
            s[nt][1] = __expf(s[nt][1] - mn0);
            s[nt][2] = __expf(s[nt][2] - mn1);
            s[nt][3] = __expf(s[nt][3] - mn1);
            rs0 += s[nt][0] + s[nt][1];
            rs1 += s[nt][2] + s[nt][3];
        }
        rs0 += __shfl_xor_sync(0xFFFFFFFFu, rs0, 1);
        rs0 += __shfl_xor_sync(0xFFFFFFFFu, rs0, 2);
        rs1 += __shfl_xor_sync(0xFFFFFFFFu, rs1, 1);
        rs1 += __shfl_xor_sync(0xFFFFFFFFu, rs1, 2);
        l0 = l0 * f0 + rs0;
        l1 = l1 * f1 + rs1;
        m0 = mn0; m1 = mn1;
        #pragma unroll
        for (int dt = 0; dt < 8; ++dt) {
            o[dt][0] *= f0; o[dt][1] *= f0;
            o[dt][2] *= f1; o[dt][3] *= f1;
        }

        // ---- O += P V : redistribute P (C-frag -> A-frag) via shuffles ----
        #pragma unroll
        for (int kk = 0; kk < 8; ++kk) {
            float x0 = __shfl_sync(0xFFFFFFFFu, s[kk][0], srcA);
            float x1 = __shfl_sync(0xFFFFFFFFu, s[kk][1], srcA);
            float y0 = __shfl_sync(0xFFFFFFFFu, s[kk][2], srcA);
            float y1 = __shfl_sync(0xFFFFFFFFu, s[kk][3], srcA);
            float z0 = __shfl_sync(0xFFFFFFFFu, s[kk][0], srcB);
            float z1 = __shfl_sync(0xFFFFFFFFu, s[kk][1], srcB);
            float w0 = __shfl_sync(0xFFFFFFFFu, s[kk][2], srcB);
            float w1 = __shfl_sync(0xFFFFFFFFu, s[kk][3], srcB);
            uint32_t pa[4];
            pa[0] = f2tf(odd ? x1 : x0);
            pa[1] = f2tf(odd ? y1 : y0);
            pa[2] = f2tf(odd ? z1 : z0);
            pa[3] = f2tf(odd ? w1 : w0);
            #pragma unroll
            for (int dt = 0; dt < 8; ++dt) {
                uint32_t vb[2];
                vb[0] = __float_as_uint(vS[(kk * 8 + c) * 68 + dt * 8 + r]);
                vb[1] = __float_as_uint(vS[(kk * 8 + c + 4) * 68 + dt * 8 + r]);
                mma8(o[dt], pa, vb);
            }
        }
    }

    // ---- epilogue: normalize, write [B, L, E] ----
    float il0 = 1.f / l0, il1 = 1.f / l1;
    int b = bh >> 4, h = bh & 15;
    float* op  = outAO + ((size_t)(b * SEQ + qrow0)) * EMBED + h * HDIM;
    float* op1 = op + (size_t)8 * EMBED;
    #pragma unroll
    for (int dt = 0; dt < 8; ++dt) {
        float2 v0 = make_float2(o[dt][0] * il0, o[dt][1] * il0);
        float2 v1 = make_float2(o[dt][2] * il1, o[dt][3] * il1);
        *reinterpret_cast<float2*>(op  + dt * 8 + 2 * c) = v0;
        *reinterpret_cast<float2*>(op1 + dt * 8 + 2 * c) = v1;
    }
}

// ---------------- launch ----------------
extern "C" void kernel_launch(void* const* d_in, const int* in_sizes, int n_in,
                              void* d_out, int out_size)
{
    (void)in_sizes; (void)n_in; (void)out_size;
    const float* query = (const float*)d_in[0];
    const float* key   = (const float*)d_in[1];
    const float* value = (const float*)d_in[2];
    const float* Wq    = (const float*)d_in[3];
    const float* bq    = (const float*)d_in[4];
    const float* Wk    = (const float*)d_in[5];
    const float* bk    = (const float*)d_in[6];
    const float* Wv    = (const float*)d_in[7];
    const float* bv    = (const float*)d_in[8];
    const float* Wo    = (const float*)d_in[9];
    const float* bo    = (const float*)d_in[10];
    float* out = (float*)d_out;

    float *gq, *gk, *gv, *gao;
    cudaGetSymbolAddress((void**)&gq,  g_Q);
    cudaGetSymbolAddress((void**)&gk,  g_K);
    cudaGetSymbolAddress((void**)&gv,  g_V);
    cudaGetSymbolAddress((void**)&gao, g_AO);

    dim3 blk(256);
    dim3 gp(EMBED / 128, MROWS / 128);   // (8, 64)

    gemm_tn<1><<<gp, blk>>>(query, Wq, bq, gq);
    gemm_tn<1><<<gp, blk>>>(key,   Wk, bk, gk);
    gemm_tn<1><<<gp, blk>>>(value, Wv, bv, gv);

    attn_kernel<<<dim3(16, 64), blk>>>(gao);

    gemm_tn<0><<<gp, blk>>>(gao, Wo, bo, out);
}

// round 4
// speedup vs baseline: 1.1211x; 1.1211x over previous
#include <cuda_runtime.h>
#include <cstdint>

#define EMBED   1024
#define NHEADS  16
#define HDIM    64
#define BATCH   4
#define SEQ     2048
#define MROWS   (BATCH * SEQ)                   // 8192
#define HEADEL  (BATCH * NHEADS * SEQ * HDIM)   // 8388608
#define EE      (EMBED * EMBED)

// Scratch (static device globals: allocation-free rule).
// g_rq doubles as the attention-output buffer: it is consumed by the Q
// projection GEMM before attn_kernel writes into it.
__device__ float g_Q[HEADEL];
__device__ float g_K[HEADEL];
__device__ float g_V[HEADEL];
__device__ float g_rq[MROWS * EMBED];
__device__ float g_rk[MROWS * EMBED];
__device__ float g_rv[MROWS * EMBED];
__device__ float g_rw[4 * EE];

// ---------------- helpers ----------------
__device__ __forceinline__ uint32_t f2tf(float x) {
    uint32_t u;
    asm("cvt.rna.tf32.f32 %0, %1;" : "=r"(u) : "f"(x));
    return u;
}
__device__ __forceinline__ float tf32r(float x) {
    return __uint_as_float(f2tf(x));
}
__device__ __forceinline__ float ex2(float x) {
    float y;
    asm("ex2.approx.f32 %0, %1;" : "=f"(y) : "f"(x));
    return y;
}
__device__ __forceinline__ void mma8(float* d, const uint32_t* a, const uint32_t* b) {
    asm volatile(
        "mma.sync.aligned.m16n8k8.row.col.f32.tf32.tf32.f32 "
        "{%0,%1,%2,%3},{%4,%5,%6,%7},{%8,%9},{%0,%1,%2,%3};\n"
        : "+f"(d[0]), "+f"(d[1]), "+f"(d[2]), "+f"(d[3])
        : "r"(a[0]), "r"(a[1]), "r"(a[2]), "r"(a[3]), "r"(b[0]), "r"(b[1]));
}
__device__ __forceinline__ void cp16(float* s, const float* g) {
    uint32_t sa = (uint32_t)__cvta_generic_to_shared(s);
    asm volatile("cp.async.cg.shared.global [%0], [%1], 16;" :: "r"(sa), "l"(g));
}
#define CP_COMMIT() asm volatile("cp.async.commit_group;")
#define CP_WAIT0()  asm volatile("cp.async.wait_group 0;")

// ---------------- pre-round inputs to tf32 (rna) ----------------
__global__ void round_tf32_kernel(const float4* __restrict__ src,
                                  float4* __restrict__ dst, int n4)
{
    for (int i = blockIdx.x * blockDim.x + threadIdx.x; i < n4;
         i += gridDim.x * blockDim.x) {
        float4 v = src[i];
        dst[i] = make_float4(tf32r(v.x), tf32r(v.y), tf32r(v.z), tf32r(v.w));
    }
}

// ---------------- TN GEMM: out = X @ W^T + bias ----------------
// X: [8192,1024] rm (pre-rounded tf32), W: [1024,1024] rm (pre-rounded tf32).
// MODE 0: out[m*N+n] fp32. MODE 1: split heads, output rounded to tf32 (rna).
#define GEMM_BUF 9216            // floats per buffer (sA 128*36 + sB 128*36)
#define GEMM_SMEM (2 * GEMM_BUF * 4)

template<int MODE>
__global__ __launch_bounds__(256) void gemm_tn(const float* __restrict__ X,
                                               const float* __restrict__ W,
                                               const float* __restrict__ bias,
                                               float* __restrict__ out)
{
    constexpr int K = EMBED, N = EMBED;
    extern __shared__ float smem[];

    const int tid  = threadIdx.x;
    const int lane = tid & 31;
    const int wid  = tid >> 5;
    const int wm   = wid & 1;
    const int wn   = wid >> 1;
    const int r    = lane >> 2;
    const int c    = lane & 3;
    const int bm   = blockIdx.y * 128;
    const int bn   = blockIdx.x * 128;

    float acc[4][4][4];
    #pragma unroll
    for (int mt = 0; mt < 4; ++mt)
        #pragma unroll
        for (int nt = 0; nt < 4; ++nt)
            #pragma unroll
            for (int e = 0; e < 4; ++e) acc[mt][nt][e] = 0.f;

    // prologue: stage chunk 0
    {
        float* sA = smem;
        float* sB = smem + 4608;
        #pragma unroll
        for (int i = 0; i < 4; ++i) {
            int e = tid + i * 256, row = e >> 3, g = e & 7;
            cp16(sA + row * 36 + g * 4, X + (size_t)(bm + row) * K + g * 4);
            cp16(sB + row * 36 + g * 4, W + (size_t)(bn + row) * K + g * 4);
        }
        CP_COMMIT();
    }

    int p = 0;
    for (int ki = 0; ki < 32; ++ki) {
        CP_WAIT0();
        __syncthreads();
        if (ki + 1 < 32) {
            float* sA = smem + (p ^ 1) * GEMM_BUF;
            float* sB = sA + 4608;
            int kt = (ki + 1) * 32;
            #pragma unroll
            for (int i = 0; i < 4; ++i) {
                int e = tid + i * 256, row = e >> 3, g = e & 7;
                cp16(sA + row * 36 + g * 4, X + (size_t)(bm + row) * K + kt + g * 4);
                cp16(sB + row * 36 + g * 4, W + (size_t)(bn + row) * K + kt + g * 4);
            }
            CP_COMMIT();
        }
        const float* sA = smem + p * GEMM_BUF;
        const float* sB = sA + 4608;
        #pragma unroll
        for (int kk = 0; kk < 4; ++kk) {
            uint32_t af[4][4], bf[4][2];
            #pragma unroll
            for (int mt = 0; mt < 4; ++mt) {
                int row0 = wm * 64 + mt * 16 + r;
                af[mt][0] = __float_as_uint(sA[row0 * 36 + kk * 8 + c]);
                af[mt][1] = __float_as_uint(sA[(row0 + 8) * 36 + kk * 8 + c]);
                af[mt][2] = __float_as_uint(sA[row0 * 36 + kk * 8 + c + 4]);
                af[mt][3] = __float_as_uint(sA[(row0 + 8) * 36 + kk * 8 + c + 4]);
            }
            #pragma unroll
            for (int nt = 0; nt < 4; ++nt) {
                int n0 = wn * 32 + nt * 8 + r;
                bf[nt][0] = __float_as_uint(sB[n0 * 36 + kk * 8 + c]);
                bf[nt][1] = __float_as_uint(sB[n0 * 36 + kk * 8 + c + 4]);
            }
            #pragma unroll
            for (int mt = 0; mt < 4; ++mt)
                #pragma unroll
                for (int nt = 0; nt < 4; ++nt)
                    mma8(acc[mt][nt], af[mt], bf[nt]);
        }
        p ^= 1;
    }

    // epilogue
    #pragma unroll
    for (int mt = 0; mt < 4; ++mt) {
        int row0 = bm + wm * 64 + mt * 16 + r;
        #pragma unroll
        for (int nt = 0; nt < 4; ++nt) {
            int col = bn + wn * 32 + nt * 8 + 2 * c;
            float b0 = __ldg(bias + col);
            float b1 = __ldg(bias + col + 1);
            if (MODE == 0) {
                float2 v0 = make_float2(acc[mt][nt][0] + b0, acc[mt][nt][1] + b1);
                float2 v1 = make_float2(acc[mt][nt][2] + b0, acc[mt][nt][3] + b1);
                *reinterpret_cast<float2*>(out + (size_t)row0 * N + col)       = v0;
                *reinterpret_cast<float2*>(out + (size_t)(row0 + 8) * N + col) = v1;
            } else {
                float2 v0 = make_float2(tf32r(acc[mt][nt][0] + b0), tf32r(acc[mt][nt][1] + b1));
                float2 v1 = make_float2(tf32r(acc[mt][nt][2] + b0), tf32r(acc[mt][nt][3] + b1));
                int bb = row0 >> 11;
                int l0 = row0 & (SEQ - 1);
                int h  = col >> 6;
                int dh = col & 63;
                size_t d0 = ((size_t)(bb * NHEADS + h) * SEQ + l0) * HDIM + dh;
                *reinterpret_cast<float2*>(out + d0)            = v0;
                *reinterpret_cast<float2*>(out + d0 + 8 * HDIM) = v1;
            }
        }
    }
}

// ---------------- causal flash attention ----------------
// 128 threads (4 warps), 32 q-rows/warp -> 128-row q tile, 64-row kv tiles.
// cp.async double-buffered K/V (pre-rounded tf32 in gmem), exp2-domain softmax.
#define ATTN_BUF  8704           // floats per KV buffer (K 64*68 + V 64*68)
#define ATTN_SMEM (2 * ATTN_BUF * 4)
#define SM_C 0.18033688011112042f   // (1/sqrt(64)) * log2(e)

__global__ __launch_bounds__(128, 2) void attn_kernel(float* __restrict__ outAO)
{
    extern __shared__ float sm[];

    const int tid  = threadIdx.x;
    const int lane = tid & 31;
    const int wid  = tid >> 5;            // 4 warps, 32 q rows each
    const int r    = lane >> 2;
    const int c    = lane & 3;
    const int qt   = 15 - (int)blockIdx.x;
    const int bh   = blockIdx.y;

    const size_t base = (size_t)bh * SEQ * HDIM;
    const float* Qp = g_Q + base;
    const float* Kp = g_K + base;
    const float* Vp = g_V + base;

    // ---- stage Q (128 rows) into buf0 region, read fragments ----
    #pragma unroll
    for (int i = 0; i < 16; ++i) {
        int e = tid + i * 128, row = e >> 4, g = e & 15;
        cp16(sm + row * 68 + g * 4, Qp + (size_t)(qt * 128 + row) * HDIM + g * 4);
    }
    CP_COMMIT();
    CP_WAIT0();
    __syncthreads();

    uint32_t qa[2][8][4];
    #pragma unroll
    for (int mt = 0; mt < 2; ++mt) {
        int row0 = wid * 32 + mt * 16 + r;
        #pragma unroll
        for (int kk = 0; kk < 8; ++kk) {
            qa[mt][kk][0] = __float_as_uint(sm[row0 * 68 + kk * 8 + c]);
            qa[mt][kk][1] = __float_as_uint(sm[(row0 + 8) * 68 + kk * 8 + c]);
            qa[mt][kk][2] = __float_as_uint(sm[row0 * 68 + kk * 8 + c + 4]);
            qa[mt][kk][3] = __float_as_uint(sm[(row0 + 8) * 68 + kk * 8 + c + 4]);
        }
    }
    __syncthreads();

    float o[2][8][4];
    #pragma unroll
    for (int mt = 0; mt < 2; ++mt)
        #pragma unroll
        for (int dt = 0; dt < 8; ++dt)
            #pragma unroll
            for (int e = 0; e < 4; ++e) o[mt][dt][e] = 0.f;

    float mrow[2][2], lrow[2][2];
    #pragma unroll
    for (int mt = 0; mt < 2; ++mt) {
        mrow[mt][0] = -1e30f; mrow[mt][1] = -1e30f;
        lrow[mt][0] = 0.f;    lrow[mt][1] = 0.f;
    }

    const int qr[2] = { qt * 128 + wid * 32 + r, qt * 128 + wid * 32 + 16 + r };
    const int srcA  = (lane & ~3) | (c >> 1);
    const int srcB  = srcA + 2;
    const bool odd  = (c & 1);
    const int jt_end = 2 * qt + 1;

    // prologue: stage KV tile 0 into buf0
    {
        float* kb = sm;
        float* vb = sm + 4352;
        #pragma unroll
        for (int i = 0; i < 8; ++i) {
            int e = tid + i * 128, row = e >> 4, g = e & 15;
            cp16(kb + row * 68 + g * 4, Kp + (size_t)row * HDIM + g * 4);
            cp16(vb + row * 68 + g * 4, Vp + (size_t)row * HDIM + g * 4);
        }
        CP_COMMIT();
    }

    int p = 0;
    for (int jt = 0; jt <= jt_end; ++jt) {
        CP_WAIT0();
        __syncthreads();
        if (jt + 1 <= jt_end) {
            float* kb = sm + (p ^ 1) * ATTN_BUF;
            float* vb = kb + 4352;
            #pragma unroll
            for (int i = 0; i < 8; ++i) {
                int e = tid + i * 128, row = e >> 4, g = e & 15;
                cp16(kb + row * 68 + g * 4, Kp + (size_t)((jt + 1) * 64 + row) * HDIM + g * 4);
                cp16(vb + row * 68 + g * 4, Vp + (size_t)((jt + 1) * 64 + row) * HDIM + g * 4);
            }
            CP_COMMIT();
        }
        const float* kS = sm + p * ATTN_BUF;
        const float* vS = kS + 4352;

        // ---- S = Q K^T : 128 x 64 per CTA, 32 x 64 per warp ----
        float s[2][8][4];
        #pragma unroll
        for (int mt = 0; mt < 2; ++mt)
            #pragma unroll
            for (int nt = 0; nt < 8; ++nt)
                #pragma unroll
                for (int e = 0; e < 4; ++e) s[mt][nt][e] = 0.f;

        #pragma unroll
        for (int kk = 0; kk < 8; ++kk) {
            #pragma unroll
            for (int nt = 0; nt < 8; ++nt) {
                uint32_t bb[2];
                bb[0] = __float_as_uint(kS[(nt * 8 + r) * 68 + kk * 8 + c]);
                bb[1] = __float_as_uint(kS[(nt * 8 + r) * 68 + kk * 8 + c + 4]);
                mma8(s[0][nt], qa[0][kk], bb);
                mma8(s[1][nt], qa[1][kk], bb);
            }
        }

        // ---- causal mask ----
        if (jt >= 2 * qt) {
            #pragma unroll
            for (int mt = 0; mt < 2; ++mt)
                #pragma unroll
                for (int nt = 0; nt < 8; ++nt) {
                    int kc = jt * 64 + nt * 8 + 2 * c;
                    if (kc > qr[mt])         s[mt][nt][0] = -1e30f;
                    if (kc + 1 > qr[mt])     s[mt][nt][1] = -1e30f;
                    if (kc > qr[mt] + 8)     s[mt][nt][2] = -1e30f;
                    if (kc + 1 > qr[mt] + 8) s[mt][nt][3] = -1e30f;
                }
        }

        // ---- online softmax (exp2 domain, scale folded into FFMA) ----
        #pragma unroll
        for (int mt = 0; mt < 2; ++mt) {
            float rmax0 = -1e30f, rmax1 = -1e30f;
            #pragma unroll
            for (int nt = 0; nt < 8; ++nt) {
                rmax0 = fmaxf(rmax0, fmaxf(s[mt][nt][0], s[mt][nt][1]));
                rmax1 = fmaxf(rmax1, fmaxf(s[mt][nt][2], s[mt][nt][3]));
            }
            rmax0 = fmaxf(rmax0, __shfl_xor_sync(0xFFFFFFFFu, rmax0, 1));
            rmax0 = fmaxf(rmax0, __shfl_xor_sync(0xFFFFFFFFu, rmax0, 2));
            rmax1 = fmaxf(rmax1, __shfl_xor_sync(0xFFFFFFFFu, rmax1, 1));
            rmax1 = fmaxf(rmax1, __shfl_xor_sync(0xFFFFFFFFu, rmax1, 2));

            float mn0 = fmaxf(mrow[mt][0], rmax0);
            float mn1 = fmaxf(mrow[mt][1], rmax1);
            float f0 = ex2((mrow[mt][0] - mn0) * SM_C);
            float f1 = ex2((mrow[mt][1] - mn1) * SM_C);
            float mc0 = mn0 * SM_C, mc1 = mn1 * SM_C;
            float rs0 = 0.f, rs1 = 0.f;
            #pragma unroll
            for (int nt = 0; nt < 8; ++nt) {
                s[mt][nt][0] = ex2(fmaf(s[mt][nt][0], SM_C, -mc0));
                s[mt][nt][1] = ex2(fmaf(s[mt][nt][1], SM_C, -mc0));
                s[mt][nt][2] = ex2(fmaf(s[mt][nt][2], SM_C, -mc1));
                s[mt][nt][3] = ex2(fmaf(s[mt][nt][3], SM_C, -mc1));
                rs0 += s[mt][nt][0] + s[mt][nt][1];
                rs1 += s[mt][nt][2] + s[mt][nt][3];
            }
            rs0 += __shfl_xor_sync(0xFFFFFFFFu, rs0, 1);
            rs0 += __shfl_xor_sync(0xFFFFFFFFu, rs0, 2);
            rs1 += __shfl_xor_sync(0xFFFFFFFFu, rs1, 1);
            rs1 += __shfl_xor_sync(0xFFFFFFFFu, rs1, 2);
            lrow[mt][0] = lrow[mt][0] * f0 + rs0;
            lrow[mt][1] = lrow[mt][1] * f1 + rs1;
            mrow[mt][0] = mn0; mrow[mt][1] = mn1;
            #pragma unroll
            for (int dt = 0; dt < 8; ++dt) {
                o[mt][dt][0] *= f0; o[mt][dt][1] *= f0;
                o[mt][dt][2] *= f1; o[mt][dt][3] *= f1;
            }
        }

        // ---- O += P V ----
        #pragma unroll
        for (int kk = 0; kk < 8; ++kk) {
            uint32_t pa[2][4];
            #pragma unroll
            for (int mt = 0; mt < 2; ++mt) {
                float x0 = __shfl_sync(0xFFFFFFFFu, s[mt][kk][0], srcA);
                float x1 = __shfl_sync(0xFFFFFFFFu, s[mt][kk][1], srcA);
                float y0 = __shfl_sync(0xFFFFFFFFu, s[mt][kk][2], srcA);
                float y1 = __shfl_sync(0xFFFFFFFFu, s[mt][kk][3], srcA);
                float z0 = __shfl_sync(0xFFFFFFFFu, s[mt][kk][0], srcB);
                float z1 = __shfl_sync(0xFFFFFFFFu, s[mt][kk][1], srcB);
                float w0 = __shfl_sync(0xFFFFFFFFu, s[mt][kk][2], srcB);
                float w1 = __shfl_sync(0xFFFFFFFFu, s[mt][kk][3], srcB);
                pa[mt][0] = f2tf(odd ? x1 : x0);
                pa[mt][1] = f2tf(odd ? y1 : y0);
                pa[mt][2] = f2tf(odd ? z1 : z0);
                pa[mt][3] = f2tf(odd ? w1 : w0);
            }
            #pragma unroll
            for (int dt = 0; dt < 8; ++dt) {
                uint32_t vb[2];
                vb[0] = __float_as_uint(vS[(kk * 8 + c) * 68 + dt * 8 + r]);
                vb[1] = __float_as_uint(vS[(kk * 8 + c + 4) * 68 + dt * 8 + r]);
                mma8(o[0][dt], pa[0], vb);
                mma8(o[1][dt], pa[1], vb);
            }
        }
        p ^= 1;
    }

    // ---- epilogue: normalize, round to tf32 (feeds final GEMM), write ----
    int b = bh >> 4, h = bh & 15;
    #pragma unroll
    for (int mt = 0; mt < 2; ++mt) {
        float il0 = 1.f / lrow[mt][0], il1 = 1.f / lrow[mt][1];
        float* op  = outAO + ((size_t)(b * SEQ + qr[mt])) * EMBED + h * HDIM;
        float* op1 = op + (size_t)8 * EMBED;
        #pragma unroll
        for (int dt = 0; dt < 8; ++dt) {
            float2 v0 = make_float2(tf32r(o[mt][dt][0] * il0), tf32r(o[mt][dt][1] * il0));
            float2 v1 = make_float2(tf32r(o[mt][dt][2] * il1), tf32r(o[mt][dt][3] * il1));
            *reinterpret_cast<float2*>(op  + dt * 8 + 2 * c) = v0;
            *reinterpret_cast<float2*>(op1 + dt * 8 + 2 * c) = v1;
        }
    }
}

// ---------------- launch ----------------
extern "C" void kernel_launch(void* const* d_in, const int* in_sizes, int n_in,
                              void* d_out, int out_size)
{
    (void)in_sizes; (void)n_in; (void)out_size;
    const float* query = (const float*)d_in[0];
    const float* key   = (const float*)d_in[1];
    const float* value = (const float*)d_in[2];
    const float* Wq    = (const float*)d_in[3];
    const float* bq    = (const float*)d_in[4];
    const float* Wk    = (const float*)d_in[5];
    const float* bk    = (const float*)d_in[6];
    const float* Wv    = (const float*)d_in[7];
    const float* bv    = (const float*)d_in[8];
    const float* Wo    = (const float*)d_in[9];
    const float* bo    = (const float*)d_in[10];
    float* out = (float*)d_out;

    cudaFuncSetAttribute(gemm_tn<0>, cudaFuncAttributeMaxDynamicSharedMemorySize, GEMM_SMEM);
    cudaFuncSetAttribute(gemm_tn<1>, cudaFuncAttributeMaxDynamicSharedMemorySize, GEMM_SMEM);
    cudaFuncSetAttribute(attn_kernel, cudaFuncAttributeMaxDynamicSharedMemorySize, ATTN_SMEM);

    float *gq, *gk, *gv, *grq, *grk, *grv, *grw;
    cudaGetSymbolAddress((void**)&gq,  g_Q);
    cudaGetSymbolAddress((void**)&gk,  g_K);
    cudaGetSymbolAddress((void**)&gv,  g_V);
    cudaGetSymbolAddress((void**)&grq, g_rq);
    cudaGetSymbolAddress((void**)&grk, g_rk);
    cudaGetSymbolAddress((void**)&grv, g_rv);
    cudaGetSymbolAddress((void**)&grw, g_rw);

    const int n4x = MROWS * EMBED / 4;   // activations
    const int n4w = EE / 4;              // one weight matrix
    round_tf32_kernel<<<2048, 256>>>((const float4*)query, (float4*)grq, n4x);
    round_tf32_kernel<<<2048, 256>>>((const float4*)key,   (float4*)grk, n4x);
    round_tf32_kernel<<<2048, 256>>>((const float4*)value, (float4*)grv, n4x);
    round_tf32_kernel<<<512, 256>>>((const float4*)Wq, (float4*)(grw + 0 * EE), n4w);
    round_tf32_kernel<<<512, 256>>>((const float4*)Wk, (float4*)(grw + 1 * EE), n4w);
    round_tf32_kernel<<<512, 256>>>((const float4*)Wv, (float4*)(grw + 2 * EE), n4w);
    round_tf32_kernel<<<512, 256>>>((const float4*)Wo, (float4*)(grw + 3 * EE), n4w);

    dim3 blk(256);
    dim3 gp(EMBED / 128, MROWS / 128);   // (8, 64)

    gemm_tn<1><<<gp, blk, GEMM_SMEM>>>(grq, grw + 0 * EE, bq, gq);
    gemm_tn<1><<<gp, blk, GEMM_SMEM>>>(grk, grw + 1 * EE, bk, gk);
    gemm_tn<1><<<gp, blk, GEMM_SMEM>>>(grv, grw + 2 * EE, bv, gv);

    // attention output reuses g_rq (Q projection already consumed it)
    attn_kernel<<<dim3(16, 64), dim3(128), ATTN_SMEM>>>(grq);

    gemm_tn<0><<<gp, blk, GEMM_SMEM>>>(grq, grw + 3 * EE, bo, out);
}